// round 10
// baseline (speedup 1.0000x reference)
#include <cuda_runtime.h>
#include <stdint.h>

// SkipGramNS: out[i] = dot(cxt_weight[ctx_idx[i]], tgt_weight[tgt_idx[i]])
// N=1e6, D=128, V=1e5.
//
// R10: we are at the L2 (LTS) sector roofline (~32 sectors/pair; R3/R6/R9 all
// show identical absolute L2 work). Reduce sectors via locality:
//   K1 histogram of ci>>5 (buckets of 32 context rows = 16KB)
//   K2 exclusive scan (one block)
//   K3 scatter (ci, ti, orig_idx) into bucket-ordered scratch
//   K4 one CTA per bucket: the bucket's <=32 context rows become L1-resident
//      across their ~10x reuse -> C-row L2 sectors drop ~10x.
// Scratch lives in __device__ globals (no allocation). Deterministic output:
// scatter order varies but each pair's value depends only on (ci, ti).

#define D_SHIFT 7           // D = 128
#define B_SHIFT 5           // 32 rows per bucket
#define BMAX    4096        // supports V <= 131072
#define NMAX    (1 << 21)   // supports n <= 2,097,152

__device__ int  g_hist[BMAX];
__device__ int  g_start[BMAX + 1];
__device__ int  g_cursor[BMAX];
__device__ int4 g_scratch[NMAX];

// ---------- K1: histogram ----------
__global__ void hist_kernel(const int* __restrict__ ci, int n)
{
    int i = blockIdx.x * blockDim.x + threadIdx.x;
    if (i < n)
        atomicAdd(&g_hist[__ldg(&ci[i]) >> B_SHIFT], 1);
}

// ---------- K2: exclusive scan over BMAX=4096 (one block, 1024 thr) ----------
__global__ void scan_kernel(int n)
{
    __shared__ int wsum[32];
    const int t    = threadIdx.x;
    const int lane = t & 31;
    const int warp = t >> 5;

    int4 v = *reinterpret_cast<int4*>(&g_hist[t * 4]);
    const int tot = v.x + v.y + v.z + v.w;

    // inclusive warp scan of tot
    int incl = tot;
    #pragma unroll
    for (int o = 1; o < 32; o <<= 1) {
        int u = __shfl_up_sync(0xFFFFFFFFu, incl, o);
        if (lane >= o) incl += u;
    }
    if (lane == 31) wsum[warp] = incl;
    __syncthreads();
    if (warp == 0) {
        int w = wsum[lane];
        int wi = w;
        #pragma unroll
        for (int o = 1; o < 32; o <<= 1) {
            int u = __shfl_up_sync(0xFFFFFFFFu, wi, o);
            if (lane >= o) wi += u;
        }
        wsum[lane] = wi - w;     // exclusive warp base
    }
    __syncthreads();

    const int base = wsum[warp] + incl - tot;  // exclusive prefix of this thread's 4
    int4 st;
    st.x = base;
    st.y = base + v.x;
    st.z = base + v.x + v.y;
    st.w = base + v.x + v.y + v.z;
    *reinterpret_cast<int4*>(&g_start[t * 4])  = st;
    *reinterpret_cast<int4*>(&g_cursor[t * 4]) = st;
    if (t == 1023) g_start[BMAX] = base + tot;   // == n
}

// ---------- K3: scatter pairs into bucket order ----------
__global__ void scatter_kernel(const int* __restrict__ ci,
                               const int* __restrict__ ti, int n)
{
    int i = blockIdx.x * blockDim.x + threadIdx.x;
    if (i >= n) return;
    const int c = __ldg(&ci[i]);
    const int t = __ldg(&ti[i]);
    const int p = atomicAdd(&g_cursor[c >> B_SHIFT], 1);
    g_scratch[p] = make_int4(c, t, i, 0);
}

// ---------- K4: one CTA per bucket, R3 load geometry ----------
__global__ void __launch_bounds__(512)
dot_kernel(const float* __restrict__ cxt_w,
           const float* __restrict__ tgt_w,
           float* __restrict__ out)
{
    const int b = blockIdx.x;
    const int s = g_start[b];
    const int e = g_start[b + 1];

    const int lane  = threadIdx.x & 31;
    const int warp  = threadIdx.x >> 5;   // 0..15
    const int group = lane >> 3;          // 0..3
    const int j     = lane & 7;           // 0..7

    for (int base = s + warp * 4; base < e; base += 64) {
        const int p  = base + group;
        const bool ok = (p < e);

        int4 pr = ok ? g_scratch[p] : make_int4(0, 0, 0, 0);

        const float4* __restrict__ cv =
            reinterpret_cast<const float4*>(cxt_w + ((long long)pr.x << D_SHIFT));
        const float4* __restrict__ tv =
            reinterpret_cast<const float4*>(tgt_w + ((long long)pr.y << D_SHIFT));

        // 8 LDG.128, each covering one full 128B line per row (R3 geometry)
        const float4 a0 = __ldg(&cv[j]);
        const float4 a1 = __ldg(&cv[j +  8]);
        const float4 a2 = __ldg(&cv[j + 16]);
        const float4 a3 = __ldg(&cv[j + 24]);
        const float4 b0 = __ldg(&tv[j]);
        const float4 b1 = __ldg(&tv[j +  8]);
        const float4 b2 = __ldg(&tv[j + 16]);
        const float4 b3 = __ldg(&tv[j + 24]);

        float s0 = 0.f, s1 = 0.f, s2 = 0.f, s3 = 0.f;
        s0 = fmaf(a0.x, b0.x, s0); s0 = fmaf(a0.y, b0.y, s0);
        s0 = fmaf(a0.z, b0.z, s0); s0 = fmaf(a0.w, b0.w, s0);
        s1 = fmaf(a1.x, b1.x, s1); s1 = fmaf(a1.y, b1.y, s1);
        s1 = fmaf(a1.z, b1.z, s1); s1 = fmaf(a1.w, b1.w, s1);
        s2 = fmaf(a2.x, b2.x, s2); s2 = fmaf(a2.y, b2.y, s2);
        s2 = fmaf(a2.z, b2.z, s2); s2 = fmaf(a2.w, b2.w, s2);
        s3 = fmaf(a3.x, b3.x, s3); s3 = fmaf(a3.y, b3.y, s3);
        s3 = fmaf(a3.z, b3.z, s3); s3 = fmaf(a3.w, b3.w, s3);
        float sv = (s0 + s1) + (s2 + s3);

        sv += __shfl_xor_sync(0xFFFFFFFFu, sv, 4);
        sv += __shfl_xor_sync(0xFFFFFFFFu, sv, 2);
        sv += __shfl_xor_sync(0xFFFFFFFFu, sv, 1);

        if (ok && j == 0)
            __stcs(&out[pr.z], sv);
    }
}

// ---------- fallback: proven direct kernel (R3 geometry, ~70us) ----------
__global__ void __launch_bounds__(256)
direct_kernel(const int* __restrict__ ctx_idx,
              const int* __restrict__ tgt_idx,
              const float* __restrict__ cxt_w,
              const float* __restrict__ tgt_w,
              float* __restrict__ out, int n)
{
    const int warp_id = (blockIdx.x * blockDim.x + threadIdx.x) >> 5;
    const int lane    = threadIdx.x & 31;
    const int group   = lane >> 3;
    const int j       = lane & 7;
    const int pair    = warp_id * 4 + group;
    if (pair >= n) return;

    const long long c = (long long)__ldg(&ctx_idx[pair]);
    const long long t = (long long)__ldg(&tgt_idx[pair]);
    const float4* __restrict__ cv = reinterpret_cast<const float4*>(cxt_w + c * 128);
    const float4* __restrict__ tv = reinterpret_cast<const float4*>(tgt_w + t * 128);

    const float4 a0 = __ldg(&cv[j]);
    const float4 a1 = __ldg(&cv[j +  8]);
    const float4 a2 = __ldg(&cv[j + 16]);
    const float4 a3 = __ldg(&cv[j + 24]);
    const float4 b0 = __ldg(&tv[j]);
    const float4 b1 = __ldg(&tv[j +  8]);
    const float4 b2 = __ldg(&tv[j + 16]);
    const float4 b3 = __ldg(&tv[j + 24]);

    float s0 = 0.f, s1 = 0.f, s2 = 0.f, s3 = 0.f;
    s0 = fmaf(a0.x, b0.x, s0); s0 = fmaf(a0.y, b0.y, s0);
    s0 = fmaf(a0.z, b0.z, s0); s0 = fmaf(a0.w, b0.w, s0);
    s1 = fmaf(a1.x, b1.x, s1); s1 = fmaf(a1.y, b1.y, s1);
    s1 = fmaf(a1.z, b1.z, s1); s1 = fmaf(a1.w, b1.w, s1);
    s2 = fmaf(a2.x, b2.x, s2); s2 = fmaf(a2.y, b2.y, s2);
    s2 = fmaf(a2.z, b2.z, s2); s2 = fmaf(a2.w, b2.w, s2);
    s3 = fmaf(a3.x, b3.x, s3); s3 = fmaf(a3.y, b3.y, s3);
    s3 = fmaf(a3.z, b3.z, s3); s3 = fmaf(a3.w, b3.w, s3);
    float s = (s0 + s1) + (s2 + s3);

    s += __shfl_xor_sync(0xFFFFFFFFu, s, 4);
    s += __shfl_xor_sync(0xFFFFFFFFu, s, 2);
    s += __shfl_xor_sync(0xFFFFFFFFu, s, 1);

    if (j == 0)
        __stcs(&out[pair], s);
}

extern "C" void kernel_launch(void* const* d_in, const int* in_sizes, int n_in,
                              void* d_out, int out_size)
{
    const int*   ctx_idx = (const int*)d_in[0];
    const int*   tgt_idx = (const int*)d_in[1];
    const float* cxt_w   = (const float*)d_in[2];
    const float* tgt_w   = (const float*)d_in[3];
    float*       out     = (float*)d_out;

    const int n = in_sizes[0];                 // 1,000,000 pairs
    const int V = in_sizes[2] >> D_SHIFT;      // 100,000 rows

    const bool shapes_ok = (n > 0) && (n <= NMAX) &&
                           ((in_sizes[2] & 127) == 0) &&
                           (V <= (BMAX << B_SHIFT));

    if (shapes_ok) {
        void* hp = nullptr;
        cudaGetSymbolAddress(&hp, g_hist);
        cudaMemsetAsync(hp, 0, BMAX * sizeof(int));

        hist_kernel<<<(n + 255) / 256, 256>>>(ctx_idx, n);
        scan_kernel<<<1, 1024>>>(n);
        scatter_kernel<<<(n + 255) / 256, 256>>>(ctx_idx, tgt_idx, n);

        const int B = (V + 31) >> B_SHIFT;     // buckets actually populated
        dot_kernel<<<B, 512>>>(cxt_w, tgt_w, out);
    } else {
        const int threads = 256;
        const int pairs_per_block = (threads / 32) * 4;
        const int blocks = (n + pairs_per_block - 1) / pairs_per_block;
        direct_kernel<<<blocks, threads>>>(ctx_idx, tgt_idx, cxt_w, tgt_w, out, n);
    }
}

// round 11
// speedup vs baseline: 1.4420x; 1.4420x over previous
#include <cuda_runtime.h>
#include <stdint.h>

// SkipGramNS: out[i] = dot(cxt_weight[ctx_idx[i]], tgt_weight[tgt_idx[i]])
// N=1e6, D=128, V=1e5.
//
// R11 model: binder is L1tex wavefronts (8/pair: 2 rows x 4 x 128B lines),
// ~2.07 cyc/wf, independent of L1 hit/miss (R10 proved L2-miss reduction is
// time-neutral). Fix: remove the C-row reads from the L1tex path.
//   K0 memset cursors
//   K1 scatter pairs into fixed-capacity buckets of 32 context rows
//      (packed u64: idx|ti<<20|ci<<40), overflow -> side list
//   K2 dot: one CTA per bucket; stage the bucket's 32 C rows (16KB) in SMEM
//      once; per pair: T via 4x LDG.128 (4 wavefronts), C via LDS.128
//      (smem crossbar, separate pipe).
//   K3 overflow sweep (normally empty).

#define D_SHIFT  7            // D = 128
#define B_SHIFT  5            // 32 rows per bucket
#define ROWS_PB  32
#define BMAX     4096         // supports V <= 131072
#define SLOTS    512          // Poisson(320) => P(overflow) ~ 0
#define NMAX_    (1 << 20)    // supports n <= 1,048,576

__device__ int                g_cursor[BMAX];
__device__ int                g_ovcnt;
__device__ unsigned long long g_scratch[BMAX * SLOTS];   // 16MB
__device__ unsigned long long g_ovf[NMAX_];              // 8MB

// ---------- K1: scatter ----------
__global__ void scatter_kernel(const int* __restrict__ ci,
                               const int* __restrict__ ti, int n)
{
    int i = blockIdx.x * blockDim.x + threadIdx.x;
    if (i >= n) return;
    const int c = __ldg(&ci[i]);
    const int t = __ldg(&ti[i]);
    const unsigned long long v =
        (unsigned long long)i |
        ((unsigned long long)t << 20) |
        ((unsigned long long)c << 40);
    const int b = c >> B_SHIFT;
    const int s = atomicAdd(&g_cursor[b], 1);
    if (s < SLOTS) g_scratch[(size_t)b * SLOTS + s] = v;
    else           g_ovf[atomicAdd(&g_ovcnt, 1)] = v;
}

// ---------- K2: dot, one CTA per bucket, C rows staged in SMEM ----------
__global__ void __launch_bounds__(256)
dot_kernel(const float* __restrict__ cxt_w,
           const float* __restrict__ tgt_w,
           float* __restrict__ out, int V)
{
    __shared__ float cs[ROWS_PB * 128];   // 16KB

    const int b   = blockIdx.x;
    const int cnt = min(g_cursor[b], SLOTS);
    const unsigned long long* __restrict__ bucket = g_scratch + (size_t)b * SLOTS;

    // stage this bucket's C rows (coalesced float4)
    {
        const int r0    = b << B_SHIFT;
        const int nrows = min(ROWS_PB, V - r0);
        if (nrows > 0) {
            const float4* __restrict__ src =
                reinterpret_cast<const float4*>(cxt_w + ((size_t)r0 << D_SHIFT));
            float4* dst = reinterpret_cast<float4*>(cs);
            const int nv = nrows * 32;            // float4 per bucket
            for (int k = threadIdx.x; k < nv; k += 256)
                dst[k] = __ldg(&src[k]);
        }
    }
    __syncthreads();
    if (cnt == 0) return;

    const int lane  = threadIdx.x & 31;
    const int warp  = threadIdx.x >> 5;   // 0..7
    const int group = lane >> 3;          // 0..3
    const int j     = lane & 7;           // 0..7

    for (int base = warp * 4; base < cnt; base += 32) {
        const int p   = base + group;
        const bool ok = (p < cnt);
        const unsigned long long v = __ldg(&bucket[ok ? p : 0]);

        const int idx = (int)(v & 0xFFFFFu);
        const int ti  = (int)((v >> 20) & 0xFFFFFu);
        const int cl  = (int)(v >> 40) & (ROWS_PB - 1);

        const float4* __restrict__ tv =
            reinterpret_cast<const float4*>(tgt_w + ((size_t)ti << D_SHIFT));
        const float4* __restrict__ cv =
            reinterpret_cast<const float4*>(cs + cl * 128);

        // T: 4 LDG.128, each one full 128B line per row (4 wavefronts/pair)
        const float4 b0 = __ldg(&tv[j]);
        const float4 b1 = __ldg(&tv[j +  8]);
        const float4 b2 = __ldg(&tv[j + 16]);
        const float4 b3 = __ldg(&tv[j + 24]);
        // C: from SMEM (separate crossbar pipe)
        const float4 a0 = cv[j];
        const float4 a1 = cv[j +  8];
        const float4 a2 = cv[j + 16];
        const float4 a3 = cv[j + 24];

        float s0 = 0.f, s1 = 0.f, s2 = 0.f, s3 = 0.f;
        s0 = fmaf(a0.x, b0.x, s0); s0 = fmaf(a0.y, b0.y, s0);
        s0 = fmaf(a0.z, b0.z, s0); s0 = fmaf(a0.w, b0.w, s0);
        s1 = fmaf(a1.x, b1.x, s1); s1 = fmaf(a1.y, b1.y, s1);
        s1 = fmaf(a1.z, b1.z, s1); s1 = fmaf(a1.w, b1.w, s1);
        s2 = fmaf(a2.x, b2.x, s2); s2 = fmaf(a2.y, b2.y, s2);
        s2 = fmaf(a2.z, b2.z, s2); s2 = fmaf(a2.w, b2.w, s2);
        s3 = fmaf(a3.x, b3.x, s3); s3 = fmaf(a3.y, b3.y, s3);
        s3 = fmaf(a3.z, b3.z, s3); s3 = fmaf(a3.w, b3.w, s3);
        float sv = (s0 + s1) + (s2 + s3);

        sv += __shfl_xor_sync(0xFFFFFFFFu, sv, 4);
        sv += __shfl_xor_sync(0xFFFFFFFFu, sv, 2);
        sv += __shfl_xor_sync(0xFFFFFFFFu, sv, 1);

        if (ok && j == 0)
            __stcs(&out[idx], sv);
    }
}

// ---------- K3: overflow sweep (R3 geometry; normally 0 pairs) ----------
__global__ void __launch_bounds__(256)
ovf_kernel(const float* __restrict__ cxt_w,
           const float* __restrict__ tgt_w,
           float* __restrict__ out)
{
    const int m = g_ovcnt;
    if (m == 0) return;

    const int lane  = threadIdx.x & 31;
    const int group = lane >> 3;
    const int j     = lane & 7;
    const int warp_g = (blockIdx.x * blockDim.x + threadIdx.x) >> 5;
    const int nwarps = (gridDim.x * blockDim.x) >> 5;

    for (int base = warp_g * 4; base < m; base += nwarps * 4) {
        const int p   = base + group;
        const bool ok = (p < m);
        const unsigned long long v = g_ovf[ok ? p : 0];

        const int idx = (int)(v & 0xFFFFFu);
        const int ti  = (int)((v >> 20) & 0xFFFFFu);
        const int ci  = (int)(v >> 40);

        const float4* __restrict__ tv =
            reinterpret_cast<const float4*>(tgt_w + ((size_t)ti << D_SHIFT));
        const float4* __restrict__ cv =
            reinterpret_cast<const float4*>(cxt_w + ((size_t)ci << D_SHIFT));

        float sv = 0.f;
        #pragma unroll
        for (int k = 0; k < 4; k++) {
            const float4 a = __ldg(&cv[j + 8 * k]);
            const float4 b = __ldg(&tv[j + 8 * k]);
            sv = fmaf(a.x, b.x, sv); sv = fmaf(a.y, b.y, sv);
            sv = fmaf(a.z, b.z, sv); sv = fmaf(a.w, b.w, sv);
        }
        sv += __shfl_xor_sync(0xFFFFFFFFu, sv, 4);
        sv += __shfl_xor_sync(0xFFFFFFFFu, sv, 2);
        sv += __shfl_xor_sync(0xFFFFFFFFu, sv, 1);

        if (ok && j == 0)
            __stcs(&out[idx], sv);
    }
}

// ---------- fallback: proven direct kernel (R3 geometry, ~70us) ----------
__global__ void __launch_bounds__(256)
direct_kernel(const int* __restrict__ ctx_idx,
              const int* __restrict__ tgt_idx,
              const float* __restrict__ cxt_w,
              const float* __restrict__ tgt_w,
              float* __restrict__ out, int n)
{
    const int warp_id = (blockIdx.x * blockDim.x + threadIdx.x) >> 5;
    const int lane    = threadIdx.x & 31;
    const int group   = lane >> 3;
    const int j       = lane & 7;
    const int pair    = warp_id * 4 + group;
    if (pair >= n) return;

    const long long c = (long long)__ldg(&ctx_idx[pair]);
    const long long t = (long long)__ldg(&tgt_idx[pair]);
    const float4* __restrict__ cv = reinterpret_cast<const float4*>(cxt_w + c * 128);
    const float4* __restrict__ tv = reinterpret_cast<const float4*>(tgt_w + t * 128);

    float s = 0.f;
    #pragma unroll
    for (int k = 0; k < 4; k++) {
        const float4 a = __ldg(&cv[j + 8 * k]);
        const float4 b = __ldg(&tv[j + 8 * k]);
        s = fmaf(a.x, b.x, s); s = fmaf(a.y, b.y, s);
        s = fmaf(a.z, b.z, s); s = fmaf(a.w, b.w, s);
    }
    s += __shfl_xor_sync(0xFFFFFFFFu, s, 4);
    s += __shfl_xor_sync(0xFFFFFFFFu, s, 2);
    s += __shfl_xor_sync(0xFFFFFFFFu, s, 1);

    if (j == 0)
        __stcs(&out[pair], s);
}

extern "C" void kernel_launch(void* const* d_in, const int* in_sizes, int n_in,
                              void* d_out, int out_size)
{
    const int*   ctx_idx = (const int*)d_in[0];
    const int*   tgt_idx = (const int*)d_in[1];
    const float* cxt_w   = (const float*)d_in[2];
    const float* tgt_w   = (const float*)d_in[3];
    float*       out     = (float*)d_out;

    const int n = in_sizes[0];                 // 1,000,000 pairs
    const int V = in_sizes[2] >> D_SHIFT;      // 100,000 rows

    const bool shapes_ok = (n > 0) && (n <= NMAX_) &&
                           ((in_sizes[2] & 127) == 0) &&
                           (V <= (BMAX << B_SHIFT)) && (V <= (1 << 20));

    if (shapes_ok) {
        void* cp = nullptr; void* op = nullptr;
        cudaGetSymbolAddress(&cp, g_cursor);
        cudaGetSymbolAddress(&op, g_ovcnt);
        cudaMemsetAsync(cp, 0, BMAX * sizeof(int));
        cudaMemsetAsync(op, 0, sizeof(int));

        scatter_kernel<<<(n + 255) / 256, 256>>>(ctx_idx, tgt_idx, n);

        const int NB = (V + ROWS_PB - 1) >> B_SHIFT;
        dot_kernel<<<NB, 256>>>(cxt_w, tgt_w, out, V);
        ovf_kernel<<<64, 256>>>(cxt_w, tgt_w, out);
    } else {
        const int threads = 256;
        const int pairs_per_block = (threads / 32) * 4;
        const int blocks = (n + pairs_per_block - 1) / pairs_per_block;
        direct_kernel<<<blocks, threads>>>(ctx_idx, tgt_idx, cxt_w, tgt_w, out, n);
    }
}